// round 12
// baseline (speedup 1.0000x reference)
#include <cuda_runtime.h>
#include <cuda_bf16.h>
#include <cuda_fp16.h>
#include <math.h>
#include <stdint.h>

#define NNODES 50000
#define EMAX   800000
#define FDIM   128
#define ODIM   32
#define PAD    136          // bf16 elems per padded smem row (272B stride, conflict-free ldmatrix)
#define BPAD32 40           // pad for 32-wide B tile (80B stride, conflict-free)
#define NSCANB ((NNODES + 1023) / 1024)   // 49

// ---------------- scratch (static device memory) ----------------
__device__ __half g_h [(size_t)NNODES * FDIM];    // fp16 activations (gather-bound)
__device__ float  g_agg[(size_t)NNODES * FDIM];
__device__ float  g_xc [(size_t)NNODES * FDIM];
__device__ __half g_h2 [(size_t)NNODES * ODIM];
__device__ float  g_dis [NNODES];
__device__ float  g_sum  [2][FDIM];
__device__ float  g_sumsq[2][FDIM];
__device__ int    g_cnt [NNODES];
__device__ int    g_cur [NNODES];
__device__ int    g_off [NNODES + 1];
__device__ int    g_esrc[EMAX];
__device__ float  g_enorm[EMAX];                  // dis[src]*dis[dst] per CSR slot
__device__ int    g_bsum[64];
__device__ int    g_is64;
// pre-split bf16 W images (row-major [k][n]), packed: W0(16384) W1(16384) W2(4096)
__device__ __nv_bfloat16 g_whi[128 * 128 * 2 + 128 * 32];
__device__ __nv_bfloat16 g_wlo[128 * 128 * 2 + 128 * 32];

// ---------------- helpers ----------------
__device__ __forceinline__ int ld_idx(const void* ei, long long pos, int is64) {
    if (is64) return (int)((const long long*)ei)[pos];
    return ((const int*)ei)[pos];
}
__device__ __forceinline__ uint32_t smem_u32(const void* p) {
    uint32_t a;
    asm("{ .reg .u64 t; cvta.to.shared.u64 t, %1; cvt.u32.u64 %0, t; }" : "=r"(a) : "l"(p));
    return a;
}
__device__ __forceinline__ void ldsm_x4(uint32_t* r, uint32_t addr) {
    asm volatile("ldmatrix.sync.aligned.m8n8.x4.shared.b16 {%0,%1,%2,%3}, [%4];"
                 : "=r"(r[0]), "=r"(r[1]), "=r"(r[2]), "=r"(r[3]) : "r"(addr));
}
__device__ __forceinline__ void ldsm_x2t(uint32_t* r, uint32_t addr) {
    asm volatile("ldmatrix.sync.aligned.m8n8.x2.trans.shared.b16 {%0,%1}, [%2];"
                 : "=r"(r[0]), "=r"(r[1]) : "r"(addr));
}
__device__ __forceinline__ void mma_bf16(float* c, const uint32_t* a, const uint32_t* b) {
    asm volatile("mma.sync.aligned.m16n8k16.row.col.f32.bf16.bf16.f32 "
                 "{%0,%1,%2,%3}, {%4,%5,%6,%7}, {%8,%9}, {%0,%1,%2,%3};"
                 : "+f"(c[0]), "+f"(c[1]), "+f"(c[2]), "+f"(c[3])
                 : "r"(a[0]), "r"(a[1]), "r"(a[2]), "r"(a[3]), "r"(b[0]), "r"(b[1]));
}
__device__ __forceinline__ void split4(float4 v, uint2& hi, uint2& lo) {
    __nv_bfloat16 h0 = __float2bfloat16(v.x), h1 = __float2bfloat16(v.y);
    __nv_bfloat16 h2 = __float2bfloat16(v.z), h3 = __float2bfloat16(v.w);
    __nv_bfloat16 l0 = __float2bfloat16(v.x - __bfloat162float(h0));
    __nv_bfloat16 l1 = __float2bfloat16(v.y - __bfloat162float(h1));
    __nv_bfloat16 l2 = __float2bfloat16(v.z - __bfloat162float(h2));
    __nv_bfloat16 l3 = __float2bfloat16(v.w - __bfloat162float(h3));
    __nv_bfloat162 hp0 = __halves2bfloat162(h0, h1), hp1 = __halves2bfloat162(h2, h3);
    __nv_bfloat162 lp0 = __halves2bfloat162(l0, l1), lp1 = __halves2bfloat162(l2, l3);
    hi = make_uint2(*(uint32_t*)&hp0, *(uint32_t*)&hp1);
    lo = make_uint2(*(uint32_t*)&lp0, *(uint32_t*)&lp1);
}

// ---------------- preprocessing ----------------
__global__ void k_pre0(const unsigned* __restrict__ w) {
    int i = blockIdx.x * blockDim.x + threadIdx.x;
    if (i < NNODES) { g_cnt[i] = 0; g_cur[i] = 0; }
    if (blockIdx.x == 0) {
        __shared__ int s;
        if (threadIdx.x == 0) s = 1;
        __syncthreads();
        for (int j = threadIdx.x; j < 1024; j += blockDim.x)
            if (w[2 * j + 1] != 0u) atomicAnd(&s, 0);
        __syncthreads();
        if (threadIdx.x == 0) g_is64 = s;
    }
    if (blockIdx.x == 1 && threadIdx.x < FDIM) {
        g_sum[0][threadIdx.x] = 0.0f; g_sum[1][threadIdx.x] = 0.0f;
        g_sumsq[0][threadIdx.x] = 0.0f; g_sumsq[1][threadIdx.x] = 0.0f;
    }
}
__global__ void k_hist(const void* __restrict__ ei, int E) {
    int e = blockIdx.x * blockDim.x + threadIdx.x;
    if (e >= E) return;
    int dst = ld_idx(ei, (long long)E + e, g_is64);
    atomicAdd(&g_cnt[dst], 1);
}
__global__ void k_bsum() {
    __shared__ int red[256];
    const int base = blockIdx.x * 1024;
    const int t = threadIdx.x;
    int s = 0;
#pragma unroll
    for (int j = 0; j < 4; j++) {
        int i = base + t * 4 + j;
        if (i < NNODES) s += g_cnt[i];
    }
    red[t] = s;
    __syncthreads();
    for (int off = 128; off; off >>= 1) {
        if (t < off) red[t] += red[t + off];
        __syncthreads();
    }
    if (t == 0) g_bsum[blockIdx.x] = red[0];
}
__global__ void k_offs() {
    __shared__ int sb[64];
    __shared__ int ts[256];
    const int t = threadIdx.x;
    if (t < 64) sb[t] = (t < NSCANB) ? g_bsum[t] : 0;
    __syncthreads();
    if (t < 64) {
        for (int off = 1; off < 64; off <<= 1) {
            int x = sb[t];
            int a = (t >= off) ? sb[t - off] : 0;
            __syncthreads();
            sb[t] = x + a;
            __syncthreads();
        }
    } else {
        for (int off = 1; off < 64; off <<= 1) { __syncthreads(); __syncthreads(); }
    }
    const int base = blockIdx.x * 1024;
    int c[4];
    int s = 0;
#pragma unroll
    for (int j = 0; j < 4; j++) {
        int i = base + t * 4 + j;
        c[j] = (i < NNODES) ? g_cnt[i] : 0;
        s += c[j];
    }
    ts[t] = s;
    __syncthreads();
    for (int off = 1; off < 256; off <<= 1) {
        int x = ts[t];
        int a = (t >= off) ? ts[t - off] : 0;
        __syncthreads();
        ts[t] = x + a;
        __syncthreads();
    }
    int bofs = (blockIdx.x > 0) ? sb[blockIdx.x - 1] : 0;
    int run = bofs + ((t > 0) ? ts[t - 1] : 0);
#pragma unroll
    for (int j = 0; j < 4; j++) {
        int i = base + t * 4 + j;
        if (i < NNODES) {
            g_off[i] = run;
            run += c[j];
            g_dis[i] = rsqrtf((float)c[j] + 1.0f);
        }
    }
    if (blockIdx.x == 0 && t == 0) g_off[NNODES] = sb[63];
}
// fill CSR, also precompute per-edge norm = dis[src]*dis[dst] (runs after k_offs)
__global__ void k_fill(const void* __restrict__ ei, int E) {
    int e = blockIdx.x * blockDim.x + threadIdx.x;
    if (e >= E) return;
    int is64 = g_is64;
    int src = ld_idx(ei, e, is64);
    int dst = ld_idx(ei, (long long)E + e, is64);
    int pos = atomicAdd(&g_cur[dst], 1);
    int slot = g_off[dst] + pos;
    g_esrc[slot] = src;
    g_enorm[slot] = g_dis[src] * g_dis[dst];
}
__global__ void k_wconv(const float* __restrict__ W0, const float* __restrict__ W1,
                        const float* __restrict__ W2) {
    int idx = blockIdx.x * blockDim.x + threadIdx.x;
    const int TOT = 128 * 128 * 2 + 128 * 32;
    if (idx >= TOT) return;
    float x;
    if (idx < 16384) x = W0[idx];
    else if (idx < 32768) x = W1[idx - 16384];
    else x = W2[idx - 32768];
    __nv_bfloat16 h = __float2bfloat16(x);
    g_whi[idx] = h;
    g_wlo[idx] = __float2bfloat16(x - __bfloat162float(h));
}

// ---------------- tensor-core GEMM 64x128x128 ----------------
#define A_HI_OFF 0
#define A_LO_OFF (64 * PAD * 2)
#define B_HI_OFF (2 * 64 * PAD * 2)
#define B_LO_OFF (B_HI_OFF + 128 * PAD * 2)
#define SC_OFF   (B_LO_OFF + 128 * PAD * 2)
#define MMA_SMEM (SC_OFF + 2 * FDIM * 4)

template <int BN>
__global__ void __launch_bounds__(128, 2)
k_mma128(const float* __restrict__ XA, const __nv_bfloat16* __restrict__ Whi,
         const __nv_bfloat16* __restrict__ Wlo, __half* __restrict__ H,
         const float* __restrict__ stats_sum, const float* __restrict__ stats_sumsq,
         const float* __restrict__ gam, const float* __restrict__ bet,
         const float* __restrict__ XRES, float* __restrict__ XC, int n) {
    extern __shared__ char smem[];
    float* s_scale = (float*)(smem + SC_OFF);
    float* s_shift = s_scale + FDIM;
    const int tid = threadIdx.x;

    if (BN) {
        float inv = 1.0f / (float)n;
        float mu = stats_sum[tid] * inv;
        float var = stats_sumsq[tid] * inv - mu * mu;
        float sc = rsqrtf(var + 1e-5f) * gam[tid];
        s_scale[tid] = sc;
        s_shift[tid] = bet[tid] - mu * sc;
    }
    for (int i = tid; i < 2048; i += 128) {
        int row = i >> 4, c8 = i & 15;
        int doff = (row * PAD + c8 * 8) * 2;
        *(uint4*)(smem + B_HI_OFF + doff) = ((const uint4*)Whi)[i];
        *(uint4*)(smem + B_LO_OFF + doff) = ((const uint4*)Wlo)[i];
    }
    if (BN) __syncthreads();

    const int r0 = (int)blockIdx.x * 64;
    for (int i = tid; i < 2048; i += 128) {
        int row = i >> 5, c4 = i & 31;
        int r = r0 + row;
        float4 v = make_float4(0.f, 0.f, 0.f, 0.f);
        if (r < n) {
            if (BN) {
                float4 a = __ldg(&((const float4*)(XA + (size_t)r * 128))[c4]);
                float4 rr = __ldg(&((const float4*)(XRES + (size_t)r * 128))[c4]);
                int c = c4 * 4;
                v.x = fmaxf(fmaf(a.x, s_scale[c + 0], s_shift[c + 0]), 0.f) + rr.x;
                v.y = fmaxf(fmaf(a.y, s_scale[c + 1], s_shift[c + 1]), 0.f) + rr.y;
                v.z = fmaxf(fmaf(a.z, s_scale[c + 2], s_shift[c + 2]), 0.f) + rr.z;
                v.w = fmaxf(fmaf(a.w, s_scale[c + 3], s_shift[c + 3]), 0.f) + rr.w;
                ((float4*)(XC + (size_t)r * 128))[c4] = v;
            } else {
                v = __ldg(&((const float4*)(XA + (size_t)r * 128))[c4]);
            }
        }
        uint2 hi, lo;
        split4(v, hi, lo);
        int aoff = (row * PAD + c4 * 4) * 2;
        *(uint2*)(smem + A_HI_OFF + aoff) = hi;
        *(uint2*)(smem + A_LO_OFF + aoff) = lo;
    }
    __syncthreads();

    const int lane = tid & 31, wid = tid >> 5;
    const int m0 = (wid & 1) * 32;
    const int n0 = (wid >> 1) * 64;
    const uint32_t sb = smem_u32(smem);

    const uint32_t a_lane = (uint32_t)(lane & 15) * (PAD * 2) + ((lane & 16) ? 16u : 0u);
    const uint32_t b_lane = (uint32_t)(lane & 15) * (PAD * 2);

    float acc[2][8][4] = {};

#pragma unroll
    for (int p = 0; p < 3; p++) {
        const uint32_t abase = sb + (p == 2 ? A_LO_OFF : A_HI_OFF) + (uint32_t)m0 * (PAD * 2) + a_lane;
        const uint32_t bbase = sb + (p == 1 ? B_LO_OFF : B_HI_OFF) + b_lane + (uint32_t)n0 * 2;
#pragma unroll
        for (int ks = 0; ks < 8; ks++) {
            uint32_t ar[2][4];
            ldsm_x4(ar[0], abase + ks * 32);
            ldsm_x4(ar[1], abase + 16 * PAD * 2 + ks * 32);
            const uint32_t bk = bbase + (uint32_t)ks * 16 * PAD * 2;
#pragma unroll
            for (int nt = 0; nt < 8; nt++) {
                uint32_t br[2];
                ldsm_x2t(br, bk + nt * 16);
                mma_bf16(acc[0][nt], ar[0], br);
                mma_bf16(acc[1][nt], ar[1], br);
            }
        }
    }

    const int g = lane >> 2, tig = lane & 3;
#pragma unroll
    for (int mt = 0; mt < 2; mt++) {
#pragma unroll
        for (int half = 0; half < 2; half++) {
            int r = r0 + m0 + mt * 16 + g + half * 8;
            if (r < n) {
#pragma unroll
                for (int nt = 0; nt < 8; nt++) {
                    int c = n0 + nt * 8 + tig * 2;
                    *(__half2*)&H[(size_t)r * 128 + c] =
                        __floats2half2_rn(acc[mt][nt][half * 2], acc[mt][nt][half * 2 + 1]);
                }
            }
        }
    }
}

// ---------------- tensor-core GEMM 64x32x128 (final layer, fused BN input) ----------------
#define A32_HI 0
#define A32_LO (64 * PAD * 2)
#define B32_HI (2 * 64 * PAD * 2)
#define B32_LO (B32_HI + 128 * BPAD32 * 2)
#define SC32_OFF (B32_LO + 128 * BPAD32 * 2)
#define MMA32_SMEM (SC32_OFF + 2 * FDIM * 4)

__global__ void __launch_bounds__(128, 2)
k_mma32(const float* __restrict__ AGG, const __nv_bfloat16* __restrict__ Whi,
        const __nv_bfloat16* __restrict__ Wlo, __half* __restrict__ H2,
        const float* __restrict__ stats_sum, const float* __restrict__ stats_sumsq,
        const float* __restrict__ gam, const float* __restrict__ bet,
        const float* __restrict__ XRES, int n) {
    extern __shared__ char smem[];
    float* s_scale = (float*)(smem + SC32_OFF);
    float* s_shift = s_scale + FDIM;
    const int tid = threadIdx.x;

    {
        float inv = 1.0f / (float)n;
        float mu = stats_sum[tid] * inv;
        float var = stats_sumsq[tid] * inv - mu * mu;
        float sc = rsqrtf(var + 1e-5f) * gam[tid];
        s_scale[tid] = sc;
        s_shift[tid] = bet[tid] - mu * sc;
    }
    for (int i = tid; i < 512; i += 128) {
        int row = i >> 2, c8 = i & 3;
        int doff = (row * BPAD32 + c8 * 8) * 2;
        *(uint4*)(smem + B32_HI + doff) = ((const uint4*)Whi)[i];
        *(uint4*)(smem + B32_LO + doff) = ((const uint4*)Wlo)[i];
    }
    __syncthreads();

    const int r0 = (int)blockIdx.x * 64;
    for (int i = tid; i < 2048; i += 128) {
        int row = i >> 5, c4 = i & 31;
        int r = r0 + row;
        float4 v = make_float4(0.f, 0.f, 0.f, 0.f);
        if (r < n) {
            float4 a = __ldg(&((const float4*)(AGG + (size_t)r * 128))[c4]);
            float4 rr = __ldg(&((const float4*)(XRES + (size_t)r * 128))[c4]);
            int c = c4 * 4;
            v.x = fmaxf(fmaf(a.x, s_scale[c + 0], s_shift[c + 0]), 0.f) + rr.x;
            v.y = fmaxf(fmaf(a.y, s_scale[c + 1], s_shift[c + 1]), 0.f) + rr.y;
            v.z = fmaxf(fmaf(a.z, s_scale[c + 2], s_shift[c + 2]), 0.f) + rr.z;
            v.w = fmaxf(fmaf(a.w, s_scale[c + 3], s_shift[c + 3]), 0.f) + rr.w;
        }
        uint2 hi, lo;
        split4(v, hi, lo);
        int aoff = (row * PAD + c4 * 4) * 2;
        *(uint2*)(smem + A32_HI + aoff) = hi;
        *(uint2*)(smem + A32_LO + aoff) = lo;
    }
    __syncthreads();

    const int lane = tid & 31, wid = tid >> 5;
    const int m0 = (wid & 1) * 32;
    const int n0 = (wid >> 1) * 16;
    const uint32_t sb = smem_u32(smem);

    const uint32_t a_lane = (uint32_t)(lane & 15) * (PAD * 2) + ((lane & 16) ? 16u : 0u);
    const uint32_t b_lane = (uint32_t)(lane & 15) * (BPAD32 * 2);

    float acc[2][2][4] = {};

#pragma unroll
    for (int p = 0; p < 3; p++) {
        const uint32_t abase = sb + (p == 2 ? A32_LO : A32_HI) + (uint32_t)m0 * (PAD * 2) + a_lane;
        const uint32_t bbase = sb + (p == 1 ? B32_LO : B32_HI) + b_lane + (uint32_t)n0 * 2;
#pragma unroll
        for (int ks = 0; ks < 8; ks++) {
            uint32_t ar[2][4];
            ldsm_x4(ar[0], abase + ks * 32);
            ldsm_x4(ar[1], abase + 16 * PAD * 2 + ks * 32);
            const uint32_t bk = bbase + (uint32_t)ks * 16 * BPAD32 * 2;
#pragma unroll
            for (int nt = 0; nt < 2; nt++) {
                uint32_t br[2];
                ldsm_x2t(br, bk + nt * 16);
                mma_bf16(acc[0][nt], ar[0], br);
                mma_bf16(acc[1][nt], ar[1], br);
            }
        }
    }

    const int g = lane >> 2, tig = lane & 3;
#pragma unroll
    for (int mt = 0; mt < 2; mt++) {
#pragma unroll
        for (int half = 0; half < 2; half++) {
            int r = r0 + m0 + mt * 16 + g + half * 8;
            if (r < n) {
#pragma unroll
                for (int nt = 0; nt < 2; nt++) {
                    int c = n0 + nt * 8 + tig * 2;
                    *(__half2*)&H2[(size_t)r * 32 + c] =
                        __floats2half2_rn(acc[mt][nt][half * 2], acc[mt][nt][half * 2 + 1]);
                }
            }
        }
    }
}

// ---------------- CSR aggregation (128-wide, fp16 gather, 4-deep MLP) ----------------
__device__ __forceinline__ void acc_half8(float4& acc, const __half* __restrict__ row,
                                          int lane, float nrm) {
    uint2 u = __ldg(&((const uint2*)row)[lane]);
    float2 f0 = __half22float2(*(__half2*)&u.x);
    float2 f1 = __half22float2(*(__half2*)&u.y);
    acc.x = fmaf(f0.x, nrm, acc.x);
    acc.y = fmaf(f0.y, nrm, acc.y);
    acc.z = fmaf(f1.x, nrm, acc.z);
    acc.w = fmaf(f1.y, nrm, acc.w);
}

__global__ void k_agg128(const __half* __restrict__ H, const float* __restrict__ bias,
                         float* __restrict__ AGG, float* __restrict__ st_sum,
                         float* __restrict__ st_sumsq, int n) {
    __shared__ float s_rows[8][FDIM];
    __shared__ int s_valid[8];
    const int tid = threadIdx.x;
    const int lane = tid & 31, wid = tid >> 5;
    int v = (blockIdx.x * blockDim.x + tid) >> 5;
    const bool valid = (v < n);
    if (lane == 0) s_valid[wid] = valid ? 1 : 0;

    float4 acc = make_float4(0.f, 0.f, 0.f, 0.f);
    if (valid) {
        const float dv = g_dis[v];
        const int e0 = g_off[v], e1 = g_off[v + 1];
        acc = ((const float4*)bias)[lane];
        acc_half8(acc, H + (size_t)v * FDIM, lane, dv * dv);
        int e = e0;
        for (; e + 3 < e1; e += 4) {
            int s0 = __ldg(&g_esrc[e]);
            int s1 = __ldg(&g_esrc[e + 1]);
            int s2 = __ldg(&g_esrc[e + 2]);
            int s3 = __ldg(&g_esrc[e + 3]);
            float n0 = __ldg(&g_enorm[e]);
            float n1 = __ldg(&g_enorm[e + 1]);
            float n2 = __ldg(&g_enorm[e + 2]);
            float n3 = __ldg(&g_enorm[e + 3]);
            uint2 u0 = __ldg(&((const uint2*)(H + (size_t)s0 * FDIM))[lane]);
            uint2 u1 = __ldg(&((const uint2*)(H + (size_t)s1 * FDIM))[lane]);
            uint2 u2 = __ldg(&((const uint2*)(H + (size_t)s2 * FDIM))[lane]);
            uint2 u3 = __ldg(&((const uint2*)(H + (size_t)s3 * FDIM))[lane]);
            float2 a0 = __half22float2(*(__half2*)&u0.x), a1 = __half22float2(*(__half2*)&u0.y);
            float2 b0 = __half22float2(*(__half2*)&u1.x), b1 = __half22float2(*(__half2*)&u1.y);
            float2 c0 = __half22float2(*(__half2*)&u2.x), c1 = __half22float2(*(__half2*)&u2.y);
            float2 d0 = __half22float2(*(__half2*)&u3.x), d1 = __half22float2(*(__half2*)&u3.y);
            acc.x = fmaf(a0.x, n0, acc.x); acc.y = fmaf(a0.y, n0, acc.y);
            acc.z = fmaf(a1.x, n0, acc.z); acc.w = fmaf(a1.y, n0, acc.w);
            acc.x = fmaf(b0.x, n1, acc.x); acc.y = fmaf(b0.y, n1, acc.y);
            acc.z = fmaf(b1.x, n1, acc.z); acc.w = fmaf(b1.y, n1, acc.w);
            acc.x = fmaf(c0.x, n2, acc.x); acc.y = fmaf(c0.y, n2, acc.y);
            acc.z = fmaf(c1.x, n2, acc.z); acc.w = fmaf(c1.y, n2, acc.w);
            acc.x = fmaf(d0.x, n3, acc.x); acc.y = fmaf(d0.y, n3, acc.y);
            acc.z = fmaf(d1.x, n3, acc.z); acc.w = fmaf(d1.y, n3, acc.w);
        }
        for (; e < e1; e++) {
            int s0 = __ldg(&g_esrc[e]);
            acc_half8(acc, H + (size_t)s0 * FDIM, lane, __ldg(&g_enorm[e]));
        }
        ((float4*)(AGG + (size_t)v * FDIM))[lane] = acc;
    }
    *(float4*)&s_rows[wid][lane * 4] = acc;
    __syncthreads();

    int c = tid & 127;
    int part = tid >> 7;
    float s = 0.0f;
#pragma unroll
    for (int w = 0; w < 8; w++) {
        if (s_valid[w]) {
            float val = s_rows[w][c];
            s += part ? val * val : val;
        }
    }
    atomicAdd(part ? &st_sumsq[c] : &st_sum[c], s);
}

// ---------------- CSR aggregation (32-wide fp16) fused with log_softmax ----------------
__global__ void k_agg32_lsm(const __half* __restrict__ H2, const float* __restrict__ bias,
                            float* __restrict__ out, int n) {
    int v = (blockIdx.x * blockDim.x + threadIdx.x) >> 5;
    if (v >= n) return;
    const int lane = threadIdx.x & 31;
    const float dv = g_dis[v];
    const int e0 = g_off[v], e1 = g_off[v + 1];

    float acc = bias[lane] + __half2float(H2[(size_t)v * ODIM + lane]) * dv * dv;
    int e = e0;
    for (; e + 3 < e1; e += 4) {
        int s0 = __ldg(&g_esrc[e]);
        int s1 = __ldg(&g_esrc[e + 1]);
        int s2 = __ldg(&g_esrc[e + 2]);
        int s3 = __ldg(&g_esrc[e + 3]);
        float n0 = __ldg(&g_enorm[e]);
        float n1 = __ldg(&g_enorm[e + 1]);
        float n2 = __ldg(&g_enorm[e + 2]);
        float n3 = __ldg(&g_enorm[e + 3]);
        float a = __half2float(H2[(size_t)s0 * ODIM + lane]);
        float b = __half2float(H2[(size_t)s1 * ODIM + lane]);
        float c = __half2float(H2[(size_t)s2 * ODIM + lane]);
        float d = __half2float(H2[(size_t)s3 * ODIM + lane]);
        acc = fmaf(a, n0, acc);
        acc = fmaf(b, n1, acc);
        acc = fmaf(c, n2, acc);
        acc = fmaf(d, n3, acc);
    }
    for (; e < e1; e++) {
        int s0 = __ldg(&g_esrc[e]);
        acc = fmaf(__half2float(H2[(size_t)s0 * ODIM + lane]), __ldg(&g_enorm[e]), acc);
    }
    float m = acc;
#pragma unroll
    for (int o = 16; o; o >>= 1) m = fmaxf(m, __shfl_xor_sync(0xffffffffu, m, o));
    float ex = expf(acc - m);
    float s = ex;
#pragma unroll
    for (int o = 16; o; o >>= 1) s += __shfl_xor_sync(0xffffffffu, s, o);
    out[(size_t)v * ODIM + lane] = acc - m - logf(s);
}

// ---------------- launch ----------------
extern "C" void kernel_launch(void* const* d_in, const int* in_sizes, int n_in,
                              void* d_out, int out_size) {
    const float* x   = (const float*)d_in[0];
    const void*  ei  = d_in[1];
    const float* W0  = (const float*)d_in[2];
    const float* b0  = (const float*)d_in[3];
    const float* gm0 = (const float*)d_in[4];
    const float* be0 = (const float*)d_in[5];
    const float* W1  = (const float*)d_in[6];
    const float* b1  = (const float*)d_in[7];
    const float* gm1 = (const float*)d_in[8];
    const float* be1 = (const float*)d_in[9];
    const float* W2  = (const float*)d_in[10];
    const float* b2  = (const float*)d_in[11];
    float* out = (float*)d_out;

    const int n = in_sizes[0] / FDIM;   // 50000
    const int E = in_sizes[1] / 2;      // 800000

    __half *p_h, *p_h2;
    float *p_agg, *p_xc, *p_sum, *p_sumsq;
    cudaGetSymbolAddress((void**)&p_h, g_h);
    cudaGetSymbolAddress((void**)&p_agg, g_agg);
    cudaGetSymbolAddress((void**)&p_xc, g_xc);
    cudaGetSymbolAddress((void**)&p_h2, g_h2);
    cudaGetSymbolAddress((void**)&p_sum, g_sum);
    cudaGetSymbolAddress((void**)&p_sumsq, g_sumsq);
    __nv_bfloat16 *whi, *wlo;
    cudaGetSymbolAddress((void**)&whi, g_whi);
    cudaGetSymbolAddress((void**)&wlo, g_wlo);

    cudaFuncSetAttribute(k_mma128<0>, cudaFuncAttributeMaxDynamicSharedMemorySize, MMA_SMEM);
    cudaFuncSetAttribute(k_mma128<1>, cudaFuncAttributeMaxDynamicSharedMemorySize, MMA_SMEM);
    cudaFuncSetAttribute(k_mma32,     cudaFuncAttributeMaxDynamicSharedMemorySize, MMA32_SMEM);

    const int node_warp_blocks = (n + 7) / 8;
    const int mma_blocks = (n + 63) / 64;

    // ---- graph preprocessing ----
    k_pre0<<<(NNODES + 255) / 256, 256>>>((const unsigned*)ei);
    k_hist<<<(E + 255) / 256, 256>>>(ei, E);
    k_bsum<<<NSCANB, 256>>>();
    k_offs<<<NSCANB, 256>>>();
    k_fill<<<(E + 255) / 256, 256>>>(ei, E);
    k_wconv<<<144, 256>>>(W0, W1, W2);

    // ---- layer 0 ----
    k_mma128<0><<<mma_blocks, 128, MMA_SMEM>>>(x, whi, wlo, p_h,
                                               nullptr, nullptr, nullptr, nullptr,
                                               nullptr, nullptr, n);
    k_agg128<<<node_warp_blocks, 256>>>(p_h, b0, p_agg, p_sum, p_sumsq, n);

    // ---- layer 1 ----
    k_mma128<1><<<mma_blocks, 128, MMA_SMEM>>>(p_agg, whi + 16384, wlo + 16384, p_h,
                                               p_sum, p_sumsq, gm0, be0, x, p_xc, n);
    k_agg128<<<node_warp_blocks, 256>>>(p_h, b1, p_agg, p_sum + FDIM, p_sumsq + FDIM, n);

    // ---- final ----
    k_mma32<<<mma_blocks, 128, MMA32_SMEM>>>(p_agg, whi + 32768, wlo + 32768, p_h2,
                                             p_sum + FDIM, p_sumsq + FDIM, gm1, be1, p_xc, n);
    k_agg32_lsm<<<node_warp_blocks, 256>>>(p_h2, b2, out, n);
}

// round 14
// speedup vs baseline: 1.2186x; 1.2186x over previous
#include <cuda_runtime.h>
#include <cuda_fp16.h>
#include <math.h>
#include <stdint.h>

#define NNODES 50000
#define EMAX   800000
#define FDIM   128
#define ODIM   32
#define PAD    136          // fp16 elems per padded smem row (272B stride, conflict-free ldmatrix)
#define BPAD32 40           // pad for 32-wide B tile (80B stride, conflict-free)
#define NSCANB ((NNODES + 1023) / 1024)   // 49

// ---------------- scratch (static device memory) ----------------
__device__ __half g_h [(size_t)NNODES * FDIM];    // fp16 activations
__device__ float  g_agg[(size_t)NNODES * FDIM];
__device__ float  g_xc [(size_t)NNODES * FDIM];
__device__ __half g_h2 [(size_t)NNODES * ODIM];
__device__ float  g_dis [NNODES];
__device__ float  g_sum  [2][FDIM];
__device__ float  g_sumsq[2][FDIM];
__device__ int    g_cnt [NNODES];
__device__ int    g_cur [NNODES];
__device__ int    g_off [NNODES + 1];
__device__ int    g_esrc[EMAX];
__device__ int    g_bsum[64];
__device__ int    g_is64;
// fp16 W images (row-major [k][n]), packed: W0(16384) W1(16384) W2(4096)
__device__ __half g_wh[128 * 128 * 2 + 128 * 32];

// ---------------- helpers ----------------
__device__ __forceinline__ int ld_idx(const void* ei, long long pos, int is64) {
    if (is64) return (int)((const long long*)ei)[pos];
    return ((const int*)ei)[pos];
}
__device__ __forceinline__ uint32_t smem_u32(const void* p) {
    uint32_t a;
    asm("{ .reg .u64 t; cvta.to.shared.u64 t, %1; cvt.u32.u64 %0, t; }" : "=r"(a) : "l"(p));
    return a;
}
__device__ __forceinline__ void ldsm_x4(uint32_t* r, uint32_t addr) {
    asm volatile("ldmatrix.sync.aligned.m8n8.x4.shared.b16 {%0,%1,%2,%3}, [%4];"
                 : "=r"(r[0]), "=r"(r[1]), "=r"(r[2]), "=r"(r[3]) : "r"(addr));
}
__device__ __forceinline__ void ldsm_x2t(uint32_t* r, uint32_t addr) {
    asm volatile("ldmatrix.sync.aligned.m8n8.x2.trans.shared.b16 {%0,%1}, [%2];"
                 : "=r"(r[0]), "=r"(r[1]) : "r"(addr));
}
__device__ __forceinline__ void mma_f16(float* c, const uint32_t* a, const uint32_t* b) {
    asm volatile("mma.sync.aligned.m16n8k16.row.col.f32.f16.f16.f32 "
                 "{%0,%1,%2,%3}, {%4,%5,%6,%7}, {%8,%9}, {%0,%1,%2,%3};"
                 : "+f"(c[0]), "+f"(c[1]), "+f"(c[2]), "+f"(c[3])
                 : "r"(a[0]), "r"(a[1]), "r"(a[2]), "r"(a[3]), "r"(b[0]), "r"(b[1]));
}
__device__ __forceinline__ uint2 pack_h4(float4 v) {
    __half2 p0 = __floats2half2_rn(v.x, v.y);
    __half2 p1 = __floats2half2_rn(v.z, v.w);
    return make_uint2(*(uint32_t*)&p0, *(uint32_t*)&p1);
}

// ---------------- preprocessing ----------------
__global__ void k_pre0(const unsigned* __restrict__ w) {
    int i = blockIdx.x * blockDim.x + threadIdx.x;
    if (i < NNODES) { g_cnt[i] = 0; g_cur[i] = 0; }
    if (blockIdx.x == 0) {
        __shared__ int s;
        if (threadIdx.x == 0) s = 1;
        __syncthreads();
        for (int j = threadIdx.x; j < 1024; j += blockDim.x)
            if (w[2 * j + 1] != 0u) atomicAnd(&s, 0);
        __syncthreads();
        if (threadIdx.x == 0) g_is64 = s;
    }
    if (blockIdx.x == 1 && threadIdx.x < FDIM) {
        g_sum[0][threadIdx.x] = 0.0f; g_sum[1][threadIdx.x] = 0.0f;
        g_sumsq[0][threadIdx.x] = 0.0f; g_sumsq[1][threadIdx.x] = 0.0f;
    }
}
__global__ void k_hist(const void* __restrict__ ei, int E) {
    int e = blockIdx.x * blockDim.x + threadIdx.x;
    if (e >= E) return;
    int dst = ld_idx(ei, (long long)E + e, g_is64);
    atomicAdd(&g_cnt[dst], 1);
}
__global__ void k_bsum() {
    __shared__ int red[256];
    const int base = blockIdx.x * 1024;
    const int t = threadIdx.x;
    int s = 0;
#pragma unroll
    for (int j = 0; j < 4; j++) {
        int i = base + t * 4 + j;
        if (i < NNODES) s += g_cnt[i];
    }
    red[t] = s;
    __syncthreads();
    for (int off = 128; off; off >>= 1) {
        if (t < off) red[t] += red[t + off];
        __syncthreads();
    }
    if (t == 0) g_bsum[blockIdx.x] = red[0];
}
__global__ void k_offs() {
    __shared__ int sb[64];
    __shared__ int ts[256];
    const int t = threadIdx.x;
    if (t < 64) sb[t] = (t < NSCANB) ? g_bsum[t] : 0;
    __syncthreads();
    if (t < 64) {
        for (int off = 1; off < 64; off <<= 1) {
            int x = sb[t];
            int a = (t >= off) ? sb[t - off] : 0;
            __syncthreads();
            sb[t] = x + a;
            __syncthreads();
        }
    } else {
        for (int off = 1; off < 64; off <<= 1) { __syncthreads(); __syncthreads(); }
    }
    const int base = blockIdx.x * 1024;
    int c[4];
    int s = 0;
#pragma unroll
    for (int j = 0; j < 4; j++) {
        int i = base + t * 4 + j;
        c[j] = (i < NNODES) ? g_cnt[i] : 0;
        s += c[j];
    }
    ts[t] = s;
    __syncthreads();
    for (int off = 1; off < 256; off <<= 1) {
        int x = ts[t];
        int a = (t >= off) ? ts[t - off] : 0;
        __syncthreads();
        ts[t] = x + a;
        __syncthreads();
    }
    int bofs = (blockIdx.x > 0) ? sb[blockIdx.x - 1] : 0;
    int run = bofs + ((t > 0) ? ts[t - 1] : 0);
#pragma unroll
    for (int j = 0; j < 4; j++) {
        int i = base + t * 4 + j;
        if (i < NNODES) {
            g_off[i] = run;
            run += c[j];
            g_dis[i] = rsqrtf((float)c[j] + 1.0f);
        }
    }
    if (blockIdx.x == 0 && t == 0) g_off[NNODES] = sb[63];
}
__global__ void k_fill(const void* __restrict__ ei, int E) {
    int e = blockIdx.x * blockDim.x + threadIdx.x;
    if (e >= E) return;
    int is64 = g_is64;
    int src = ld_idx(ei, e, is64);
    int dst = ld_idx(ei, (long long)E + e, is64);
    int pos = atomicAdd(&g_cur[dst], 1);
    g_esrc[g_off[dst] + pos] = src;
}
__global__ void k_wconv(const float* __restrict__ W0, const float* __restrict__ W1,
                        const float* __restrict__ W2) {
    int idx = blockIdx.x * blockDim.x + threadIdx.x;
    const int TOT = 128 * 128 * 2 + 128 * 32;
    if (idx >= TOT) return;
    float x;
    if (idx < 16384) x = W0[idx];
    else if (idx < 32768) x = W1[idx - 16384];
    else x = W2[idx - 32768];
    g_wh[idx] = __float2half(x);
}

// ---------------- tensor-core GEMM 64x128x128 (single-pass fp16) ----------------
#define A_OFF    0
#define B_OFF    (64 * PAD * 2)                 // 17408
#define SC_OFF   (B_OFF + 128 * PAD * 2)        // 52224
#define MMA_SMEM (SC_OFF + 2 * FDIM * 4)        // 53248

template <int BN>
__global__ void __launch_bounds__(128)
k_mma128(const float* __restrict__ XA, const __half* __restrict__ W,
         __half* __restrict__ H,
         const float* __restrict__ stats_sum, const float* __restrict__ stats_sumsq,
         const float* __restrict__ gam, const float* __restrict__ bet,
         const float* __restrict__ XRES, float* __restrict__ XC, int n) {
    extern __shared__ char smem[];
    float* s_scale = (float*)(smem + SC_OFF);
    float* s_shift = s_scale + FDIM;
    const int tid = threadIdx.x;

    if (BN) {
        float inv = 1.0f / (float)n;
        float mu = stats_sum[tid] * inv;
        float var = stats_sumsq[tid] * inv - mu * mu;
        float sc = rsqrtf(var + 1e-5f) * gam[tid];
        s_scale[tid] = sc;
        s_shift[tid] = bet[tid] - mu * sc;
    }
    // stage W: 128 rows x 128 fp16 = 16 uint4 per row
    for (int i = tid; i < 2048; i += 128) {
        int row = i >> 4, c8 = i & 15;
        *(uint4*)(smem + B_OFF + (row * PAD + c8 * 8) * 2) = ((const uint4*)W)[i];
    }
    if (BN) __syncthreads();

    const int r0 = (int)blockIdx.x * 64;
    for (int i = tid; i < 2048; i += 128) {
        int row = i >> 5, c4 = i & 31;
        int r = r0 + row;
        float4 v = make_float4(0.f, 0.f, 0.f, 0.f);
        if (r < n) {
            if (BN) {
                float4 a = __ldg(&((const float4*)(XA + (size_t)r * 128))[c4]);
                float4 rr = __ldg(&((const float4*)(XRES + (size_t)r * 128))[c4]);
                int c = c4 * 4;
                v.x = fmaxf(fmaf(a.x, s_scale[c + 0], s_shift[c + 0]), 0.f) + rr.x;
                v.y = fmaxf(fmaf(a.y, s_scale[c + 1], s_shift[c + 1]), 0.f) + rr.y;
                v.z = fmaxf(fmaf(a.z, s_scale[c + 2], s_shift[c + 2]), 0.f) + rr.z;
                v.w = fmaxf(fmaf(a.w, s_scale[c + 3], s_shift[c + 3]), 0.f) + rr.w;
                ((float4*)(XC + (size_t)r * 128))[c4] = v;
            } else {
                v = __ldg(&((const float4*)(XA + (size_t)r * 128))[c4]);
            }
        }
        *(uint2*)(smem + A_OFF + (row * PAD + c4 * 4) * 2) = pack_h4(v);
    }
    __syncthreads();

    const int lane = tid & 31, wid = tid >> 5;
    const int m0 = (wid & 1) * 32;
    const int n0 = (wid >> 1) * 64;
    const uint32_t sb = smem_u32(smem);

    const uint32_t a_lane = (uint32_t)(lane & 15) * (PAD * 2) + ((lane & 16) ? 16u : 0u);
    const uint32_t b_lane = (uint32_t)(lane & 15) * (PAD * 2);

    float acc[2][8][4] = {};

    const uint32_t abase = sb + A_OFF + (uint32_t)m0 * (PAD * 2) + a_lane;
    const uint32_t bbase = sb + B_OFF + b_lane + (uint32_t)n0 * 2;
#pragma unroll
    for (int ks = 0; ks < 8; ks++) {
        uint32_t ar[2][4];
        ldsm_x4(ar[0], abase + ks * 32);
        ldsm_x4(ar[1], abase + 16 * PAD * 2 + ks * 32);
        const uint32_t bk = bbase + (uint32_t)ks * 16 * PAD * 2;
#pragma unroll
        for (int nt = 0; nt < 8; nt++) {
            uint32_t br[2];
            ldsm_x2t(br, bk + nt * 16);
            mma_f16(acc[0][nt], ar[0], br);
            mma_f16(acc[1][nt], ar[1], br);
        }
    }

    const int g = lane >> 2, tig = lane & 3;
#pragma unroll
    for (int mt = 0; mt < 2; mt++) {
#pragma unroll
        for (int half = 0; half < 2; half++) {
            int r = r0 + m0 + mt * 16 + g + half * 8;
            if (r < n) {
#pragma unroll
                for (int nt = 0; nt < 8; nt++) {
                    int c = n0 + nt * 8 + tig * 2;
                    *(__half2*)&H[(size_t)r * 128 + c] =
                        __floats2half2_rn(acc[mt][nt][half * 2], acc[mt][nt][half * 2 + 1]);
                }
            }
        }
    }
}

// ---------------- tensor-core GEMM 64x32x128 (final layer, fused BN input) ----------------
#define A32_OFF  0
#define B32_OFF  (64 * PAD * 2)                 // 17408
#define SC32_OFF (B32_OFF + 128 * BPAD32 * 2)   // 27648
#define MMA32_SMEM (SC32_OFF + 2 * FDIM * 4)    // 28672

__global__ void __launch_bounds__(128)
k_mma32(const float* __restrict__ AGG, const __half* __restrict__ W,
        __half* __restrict__ H2,
        const float* __restrict__ stats_sum, const float* __restrict__ stats_sumsq,
        const float* __restrict__ gam, const float* __restrict__ bet,
        const float* __restrict__ XRES, int n) {
    extern __shared__ char smem[];
    float* s_scale = (float*)(smem + SC32_OFF);
    float* s_shift = s_scale + FDIM;
    const int tid = threadIdx.x;

    {
        float inv = 1.0f / (float)n;
        float mu = stats_sum[tid] * inv;
        float var = stats_sumsq[tid] * inv - mu * mu;
        float sc = rsqrtf(var + 1e-5f) * gam[tid];
        s_scale[tid] = sc;
        s_shift[tid] = bet[tid] - mu * sc;
    }
    for (int i = tid; i < 512; i += 128) {
        int row = i >> 2, c8 = i & 3;
        *(uint4*)(smem + B32_OFF + (row * BPAD32 + c8 * 8) * 2) = ((const uint4*)W)[i];
    }
    __syncthreads();

    const int r0 = (int)blockIdx.x * 64;
    for (int i = tid; i < 2048; i += 128) {
        int row = i >> 5, c4 = i & 31;
        int r = r0 + row;
        float4 v = make_float4(0.f, 0.f, 0.f, 0.f);
        if (r < n) {
            float4 a = __ldg(&((const float4*)(AGG + (size_t)r * 128))[c4]);
            float4 rr = __ldg(&((const float4*)(XRES + (size_t)r * 128))[c4]);
            int c = c4 * 4;
            v.x = fmaxf(fmaf(a.x, s_scale[c + 0], s_shift[c + 0]), 0.f) + rr.x;
            v.y = fmaxf(fmaf(a.y, s_scale[c + 1], s_shift[c + 1]), 0.f) + rr.y;
            v.z = fmaxf(fmaf(a.z, s_scale[c + 2], s_shift[c + 2]), 0.f) + rr.z;
            v.w = fmaxf(fmaf(a.w, s_scale[c + 3], s_shift[c + 3]), 0.f) + rr.w;
        }
        *(uint2*)(smem + A32_OFF + (row * PAD + c4 * 4) * 2) = pack_h4(v);
    }
    __syncthreads();

    const int lane = tid & 31, wid = tid >> 5;
    const int m0 = (wid & 1) * 32;
    const int n0 = (wid >> 1) * 16;
    const uint32_t sb = smem_u32(smem);

    const uint32_t a_lane = (uint32_t)(lane & 15) * (PAD * 2) + ((lane & 16) ? 16u : 0u);
    const uint32_t b_lane = (uint32_t)(lane & 15) * (BPAD32 * 2);

    float acc[2][2][4] = {};

    const uint32_t abase = sb + A32_OFF + (uint32_t)m0 * (PAD * 2) + a_lane;
    const uint32_t bbase = sb + B32_OFF + b_lane + (uint32_t)n0 * 2;
#pragma unroll
    for (int ks = 0; ks < 8; ks++) {
        uint32_t ar[2][4];
        ldsm_x4(ar[0], abase + ks * 32);
        ldsm_x4(ar[1], abase + 16 * PAD * 2 + ks * 32);
        const uint32_t bk = bbase + (uint32_t)ks * 16 * BPAD32 * 2;
#pragma unroll
        for (int nt = 0; nt < 2; nt++) {
            uint32_t br[2];
            ldsm_x2t(br, bk + nt * 16);
            mma_f16(acc[0][nt], ar[0], br);
            mma_f16(acc[1][nt], ar[1], br);
        }
    }

    const int g = lane >> 2, tig = lane & 3;
#pragma unroll
    for (int mt = 0; mt < 2; mt++) {
#pragma unroll
        for (int half = 0; half < 2; half++) {
            int r = r0 + m0 + mt * 16 + g + half * 8;
            if (r < n) {
#pragma unroll
                for (int nt = 0; nt < 2; nt++) {
                    int c = n0 + nt * 8 + tig * 2;
                    *(__half2*)&H2[(size_t)r * 32 + c] =
                        __floats2half2_rn(acc[mt][nt][half * 2], acc[mt][nt][half * 2 + 1]);
                }
            }
        }
    }
}

// ---------------- CSR aggregation (128-wide, fp16 gather) + fused BN stats ----------------
__device__ __forceinline__ void acc_half8(float4& acc, const __half* __restrict__ row,
                                          int lane, float nrm) {
    uint2 u = ((const uint2*)row)[lane];
    float2 f0 = __half22float2(*(__half2*)&u.x);
    float2 f1 = __half22float2(*(__half2*)&u.y);
    acc.x = fmaf(f0.x, nrm, acc.x);
    acc.y = fmaf(f0.y, nrm, acc.y);
    acc.z = fmaf(f1.x, nrm, acc.z);
    acc.w = fmaf(f1.y, nrm, acc.w);
}

__global__ void k_agg128(const __half* __restrict__ H, const float* __restrict__ bias,
                         float* __restrict__ AGG, float* __restrict__ st_sum,
                         float* __restrict__ st_sumsq, int n) {
    __shared__ float s_rows[8][FDIM];
    __shared__ int s_valid[8];
    const int tid = threadIdx.x;
    const int lane = tid & 31, wid = tid >> 5;
    int v = (blockIdx.x * blockDim.x + tid) >> 5;
    const bool valid = (v < n);
    if (lane == 0) s_valid[wid] = valid ? 1 : 0;

    float4 acc = make_float4(0.f, 0.f, 0.f, 0.f);
    if (valid) {
        const float dv = g_dis[v];
        const int e0 = g_off[v], e1 = g_off[v + 1];
        acc = ((const float4*)bias)[lane];
        acc_half8(acc, H + (size_t)v * FDIM, lane, dv * dv);
        int e = e0;
        for (; e + 1 < e1; e += 2) {
            int s0 = __ldg(&g_esrc[e]);
            int s1 = __ldg(&g_esrc[e + 1]);
            float n0 = g_dis[s0] * dv;
            float n1 = g_dis[s1] * dv;
            acc_half8(acc, H + (size_t)s0 * FDIM, lane, n0);
            acc_half8(acc, H + (size_t)s1 * FDIM, lane, n1);
        }
        if (e < e1) {
            int s0 = __ldg(&g_esrc[e]);
            acc_half8(acc, H + (size_t)s0 * FDIM, lane, g_dis[s0] * dv);
        }
        ((float4*)(AGG + (size_t)v * FDIM))[lane] = acc;
    }
    *(float4*)&s_rows[wid][lane * 4] = acc;
    __syncthreads();

    int c = tid & 127;
    int part = tid >> 7;
    float s = 0.0f;
#pragma unroll
    for (int w = 0; w < 8; w++) {
        if (s_valid[w]) {
            float val = s_rows[w][c];
            s += part ? val * val : val;
        }
    }
    atomicAdd(part ? &st_sumsq[c] : &st_sum[c], s);
}

// ---------------- CSR aggregation (32-wide fp16) fused with log_softmax ----------------
__global__ void k_agg32_lsm(const __half* __restrict__ H2, const float* __restrict__ bias,
                            float* __restrict__ out, int n) {
    int v = (blockIdx.x * blockDim.x + threadIdx.x) >> 5;
    if (v >= n) return;
    const int lane = threadIdx.x & 31;
    const float dv = g_dis[v];
    const int e0 = g_off[v], e1 = g_off[v + 1];

    float acc = bias[lane] + __half2float(H2[(size_t)v * ODIM + lane]) * dv * dv;
    int e = e0;
    for (; e + 1 < e1; e += 2) {
        int s0 = __ldg(&g_esrc[e]);
        int s1 = __ldg(&g_esrc[e + 1]);
        float n0 = g_dis[s0] * dv;
        float n1 = g_dis[s1] * dv;
        float a = __half2float(H2[(size_t)s0 * ODIM + lane]);
        float b = __half2float(H2[(size_t)s1 * ODIM + lane]);
        acc = fmaf(a, n0, acc);
        acc = fmaf(b, n1, acc);
    }
    if (e < e1) {
        int s0 = __ldg(&g_esrc[e]);
        acc = fmaf(__half2float(H2[(size_t)s0 * ODIM + lane]), g_dis[s0] * dv, acc);
    }
    float m = acc;
#pragma unroll
    for (int o = 16; o; o >>= 1) m = fmaxf(m, __shfl_xor_sync(0xffffffffu, m, o));
    float ex = expf(acc - m);
    float s = ex;
#pragma unroll
    for (int o = 16; o; o >>= 1) s += __shfl_xor_sync(0xffffffffu, s, o);
    out[(size_t)v * ODIM + lane] = acc - m - logf(s);
}

// ---------------- launch ----------------
extern "C" void kernel_launch(void* const* d_in, const int* in_sizes, int n_in,
                              void* d_out, int out_size) {
    const float* x   = (const float*)d_in[0];
    const void*  ei  = d_in[1];
    const float* W0  = (const float*)d_in[2];
    const float* b0  = (const float*)d_in[3];
    const float* gm0 = (const float*)d_in[4];
    const float* be0 = (const float*)d_in[5];
    const float* W1  = (const float*)d_in[6];
    const float* b1  = (const float*)d_in[7];
    const float* gm1 = (const float*)d_in[8];
    const float* be1 = (const float*)d_in[9];
    const float* W2  = (const float*)d_in[10];
    const float* b2  = (const float*)d_in[11];
    float* out = (float*)d_out;

    const int n = in_sizes[0] / FDIM;   // 50000
    const int E = in_sizes[1] / 2;      // 800000

    __half *p_h, *p_h2, *p_wh;
    float *p_agg, *p_xc, *p_sum, *p_sumsq;
    cudaGetSymbolAddress((void**)&p_h, g_h);
    cudaGetSymbolAddress((void**)&p_agg, g_agg);
    cudaGetSymbolAddress((void**)&p_xc, g_xc);
    cudaGetSymbolAddress((void**)&p_h2, g_h2);
    cudaGetSymbolAddress((void**)&p_sum, g_sum);
    cudaGetSymbolAddress((void**)&p_sumsq, g_sumsq);
    cudaGetSymbolAddress((void**)&p_wh, g_wh);

    cudaFuncSetAttribute(k_mma128<0>, cudaFuncAttributeMaxDynamicSharedMemorySize, MMA_SMEM);
    cudaFuncSetAttribute(k_mma128<1>, cudaFuncAttributeMaxDynamicSharedMemorySize, MMA_SMEM);
    cudaFuncSetAttribute(k_mma32,     cudaFuncAttributeMaxDynamicSharedMemorySize, MMA32_SMEM);

    const int node_warp_blocks = (n + 7) / 8;
    const int mma_blocks = (n + 63) / 64;

    // ---- graph preprocessing ----
    k_pre0<<<(NNODES + 255) / 256, 256>>>((const unsigned*)ei);
    k_hist<<<(E + 255) / 256, 256>>>(ei, E);
    k_bsum<<<NSCANB, 256>>>();
    k_offs<<<NSCANB, 256>>>();
    k_fill<<<(E + 255) / 256, 256>>>(ei, E);
    k_wconv<<<144, 256>>>(W0, W1, W2);

    // ---- layer 0 ----
    k_mma128<0><<<mma_blocks, 128, MMA_SMEM>>>(x, p_wh, p_h,
                                               nullptr, nullptr, nullptr, nullptr,
                                               nullptr, nullptr, n);
    k_agg128<<<node_warp_blocks, 256>>>(p_h, b0, p_agg, p_sum, p_sumsq, n);

    // ---- layer 1 ----
    k_mma128<1><<<mma_blocks, 128, MMA_SMEM>>>(p_agg, p_wh + 16384, p_h,
                                               p_sum, p_sumsq, gm0, be0, x, p_xc, n);
    k_agg128<<<node_warp_blocks, 256>>>(p_h, b1, p_agg, p_sum + FDIM, p_sumsq + FDIM, n);

    // ---- final ----
    k_mma32<<<mma_blocks, 128, MMA32_SMEM>>>(p_agg, p_wh + 32768, p_h2,
                                             p_sum + FDIM, p_sumsq + FDIM, gm1, be1, p_xc, n);
    k_agg32_lsm<<<node_warp_blocks, 256>>>(p_h2, b2, out, n);
}

// round 15
// speedup vs baseline: 1.3474x; 1.1057x over previous
#include <cuda_runtime.h>
#include <cuda_fp16.h>
#include <math.h>
#include <stdint.h>

#define NNODES 50000
#define EMAX   800000
#define FDIM   128
#define ODIM   32
#define PAD    136          // fp16 elems per padded smem row (272B stride, conflict-free ldmatrix)
#define BPAD32 40           // pad for 32-wide B tile (80B stride, conflict-free)
#define NSCANB ((NNODES + 1023) / 1024)   // 49

// ---------------- scratch (static device memory) ----------------
__device__ __half g_h  [(size_t)NNODES * FDIM];   // fp16 activations
__device__ __half g_aggh[(size_t)NNODES * FDIM];  // fp16 aggregated conv output
__device__ __half g_xc [(size_t)NNODES * FDIM];   // fp16 residual-carry activations
__device__ __half g_h2 [(size_t)NNODES * ODIM];
__device__ float  g_dis [NNODES];
__device__ float  g_sum  [2][FDIM];
__device__ float  g_sumsq[2][FDIM];
__device__ int    g_cnt [NNODES];
__device__ int    g_cur [NNODES];
__device__ int    g_off [NNODES + 1];
__device__ int    g_esrc[EMAX];
__device__ int    g_bsum[64];
__device__ int    g_is64;
// fp16 W images (row-major [k][n]), packed: W0(16384) W1(16384) W2(4096)
__device__ __half g_wh[128 * 128 * 2 + 128 * 32];

// ---------------- side stream for graph-level fork/join ----------------
static cudaStream_t g_s1 = 0;
static cudaEvent_t  g_evF = 0, g_evJ = 0;
namespace {
struct StreamInit {
    StreamInit() {
        if (cudaStreamCreate(&g_s1) != cudaSuccess) g_s1 = 0;
        if (cudaEventCreateWithFlags(&g_evF, cudaEventDisableTiming) != cudaSuccess) g_evF = 0;
        if (cudaEventCreateWithFlags(&g_evJ, cudaEventDisableTiming) != cudaSuccess) g_evJ = 0;
    }
};
StreamInit g_stream_init;
}

// ---------------- helpers ----------------
__device__ __forceinline__ int ld_idx(const void* ei, long long pos, int is64) {
    if (is64) return (int)((const long long*)ei)[pos];
    return ((const int*)ei)[pos];
}
__device__ __forceinline__ uint32_t smem_u32(const void* p) {
    uint32_t a;
    asm("{ .reg .u64 t; cvta.to.shared.u64 t, %1; cvt.u32.u64 %0, t; }" : "=r"(a) : "l"(p));
    return a;
}
__device__ __forceinline__ void ldsm_x4(uint32_t* r, uint32_t addr) {
    asm volatile("ldmatrix.sync.aligned.m8n8.x4.shared.b16 {%0,%1,%2,%3}, [%4];"
                 : "=r"(r[0]), "=r"(r[1]), "=r"(r[2]), "=r"(r[3]) : "r"(addr));
}
__device__ __forceinline__ void ldsm_x2t(uint32_t* r, uint32_t addr) {
    asm volatile("ldmatrix.sync.aligned.m8n8.x2.trans.shared.b16 {%0,%1}, [%2];"
                 : "=r"(r[0]), "=r"(r[1]) : "r"(addr));
}
__device__ __forceinline__ void mma_f16(float* c, const uint32_t* a, const uint32_t* b) {
    asm volatile("mma.sync.aligned.m16n8k16.row.col.f32.f16.f16.f32 "
                 "{%0,%1,%2,%3}, {%4,%5,%6,%7}, {%8,%9}, {%0,%1,%2,%3};"
                 : "+f"(c[0]), "+f"(c[1]), "+f"(c[2]), "+f"(c[3])
                 : "r"(a[0]), "r"(a[1]), "r"(a[2]), "r"(a[3]), "r"(b[0]), "r"(b[1]));
}
__device__ __forceinline__ uint2 pack_h4(float4 v) {
    __half2 p0 = __floats2half2_rn(v.x, v.y);
    __half2 p1 = __floats2half2_rn(v.z, v.w);
    return make_uint2(*(uint32_t*)&p0, *(uint32_t*)&p1);
}
__device__ __forceinline__ float4 unpack_h4(uint2 u) {
    float2 f0 = __half22float2(*(__half2*)&u.x);
    float2 f1 = __half22float2(*(__half2*)&u.y);
    return make_float4(f0.x, f0.y, f1.x, f1.y);
}

// ---------------- preprocessing ----------------
__global__ void k_pre0(const unsigned* __restrict__ w) {
    int i = blockIdx.x * blockDim.x + threadIdx.x;
    if (i < NNODES) { g_cnt[i] = 0; g_cur[i] = 0; }
    if (blockIdx.x == 0) {
        __shared__ int s;
        if (threadIdx.x == 0) s = 1;
        __syncthreads();
        for (int j = threadIdx.x; j < 1024; j += blockDim.x)
            if (w[2 * j + 1] != 0u) atomicAnd(&s, 0);
        __syncthreads();
        if (threadIdx.x == 0) g_is64 = s;
    }
    if (blockIdx.x == 1 && threadIdx.x < FDIM) {
        g_sum[0][threadIdx.x] = 0.0f; g_sum[1][threadIdx.x] = 0.0f;
        g_sumsq[0][threadIdx.x] = 0.0f; g_sumsq[1][threadIdx.x] = 0.0f;
    }
}
__global__ void k_hist(const void* __restrict__ ei, int E) {
    int e = blockIdx.x * blockDim.x + threadIdx.x;
    if (e >= E) return;
    int dst = ld_idx(ei, (long long)E + e, g_is64);
    atomicAdd(&g_cnt[dst], 1);
}
__global__ void k_bsum() {
    __shared__ int red[256];
    const int base = blockIdx.x * 1024;
    const int t = threadIdx.x;
    int s = 0;
#pragma unroll
    for (int j = 0; j < 4; j++) {
        int i = base + t * 4 + j;
        if (i < NNODES) s += g_cnt[i];
    }
    red[t] = s;
    __syncthreads();
    for (int off = 128; off; off >>= 1) {
        if (t < off) red[t] += red[t + off];
        __syncthreads();
    }
    if (t == 0) g_bsum[blockIdx.x] = red[0];
}
__global__ void k_offs() {
    __shared__ int sb[64];
    __shared__ int ts[256];
    const int t = threadIdx.x;
    if (t < 64) sb[t] = (t < NSCANB) ? g_bsum[t] : 0;
    __syncthreads();
    if (t < 64) {
        for (int off = 1; off < 64; off <<= 1) {
            int x = sb[t];
            int a = (t >= off) ? sb[t - off] : 0;
            __syncthreads();
            sb[t] = x + a;
            __syncthreads();
        }
    } else {
        for (int off = 1; off < 64; off <<= 1) { __syncthreads(); __syncthreads(); }
    }
    const int base = blockIdx.x * 1024;
    int c[4];
    int s = 0;
#pragma unroll
    for (int j = 0; j < 4; j++) {
        int i = base + t * 4 + j;
        c[j] = (i < NNODES) ? g_cnt[i] : 0;
        s += c[j];
    }
    ts[t] = s;
    __syncthreads();
    for (int off = 1; off < 256; off <<= 1) {
        int x = ts[t];
        int a = (t >= off) ? ts[t - off] : 0;
        __syncthreads();
        ts[t] = x + a;
        __syncthreads();
    }
    int bofs = (blockIdx.x > 0) ? sb[blockIdx.x - 1] : 0;
    int run = bofs + ((t > 0) ? ts[t - 1] : 0);
#pragma unroll
    for (int j = 0; j < 4; j++) {
        int i = base + t * 4 + j;
        if (i < NNODES) {
            g_off[i] = run;
            run += c[j];
            g_dis[i] = rsqrtf((float)c[j] + 1.0f);
        }
    }
    if (blockIdx.x == 0 && t == 0) g_off[NNODES] = sb[63];
}
__global__ void k_fill(const void* __restrict__ ei, int E) {
    int e = blockIdx.x * blockDim.x + threadIdx.x;
    if (e >= E) return;
    int is64 = g_is64;
    int src = ld_idx(ei, e, is64);
    int dst = ld_idx(ei, (long long)E + e, is64);
    int pos = atomicAdd(&g_cur[dst], 1);
    g_esrc[g_off[dst] + pos] = src;
}
__global__ void k_wconv(const float* __restrict__ W0, const float* __restrict__ W1,
                        const float* __restrict__ W2) {
    int idx = blockIdx.x * blockDim.x + threadIdx.x;
    const int TOT = 128 * 128 * 2 + 128 * 32;
    if (idx >= TOT) return;
    float x;
    if (idx < 16384) x = W0[idx];
    else if (idx < 32768) x = W1[idx - 16384];
    else x = W2[idx - 32768];
    g_wh[idx] = __float2half(x);
}

// ---------------- tensor-core GEMM 64x128x128 (single-pass fp16) ----------------
#define A_OFF    0
#define B_OFF    (64 * PAD * 2)                 // 17408
#define SC_OFF   (B_OFF + 128 * PAD * 2)        // 52224
#define MMA_SMEM (SC_OFF + 2 * FDIM * 4)        // 53248

// BN=0: A = Xf (fp32 raw).  BN=1: A = relu(BN(Xh)) + XRES(fp32), also -> XC(fp16)
template <int BN>
__global__ void __launch_bounds__(128)
k_mma128(const float* __restrict__ Xf, const __half* __restrict__ Xh,
         const __half* __restrict__ W, __half* __restrict__ H,
         const float* __restrict__ stats_sum, const float* __restrict__ stats_sumsq,
         const float* __restrict__ gam, const float* __restrict__ bet,
         const float* __restrict__ XRES, __half* __restrict__ XC, int n) {
    extern __shared__ char smem[];
    float* s_scale = (float*)(smem + SC_OFF);
    float* s_shift = s_scale + FDIM;
    const int tid = threadIdx.x;

    if (BN) {
        float inv = 1.0f / (float)n;
        float mu = stats_sum[tid] * inv;
        float var = stats_sumsq[tid] * inv - mu * mu;
        float sc = rsqrtf(var + 1e-5f) * gam[tid];
        s_scale[tid] = sc;
        s_shift[tid] = bet[tid] - mu * sc;
    }
    for (int i = tid; i < 2048; i += 128) {
        int row = i >> 4, c8 = i & 15;
        *(uint4*)(smem + B_OFF + (row * PAD + c8 * 8) * 2) = ((const uint4*)W)[i];
    }
    if (BN) __syncthreads();

    const int r0 = (int)blockIdx.x * 64;
    for (int i = tid; i < 2048; i += 128) {
        int row = i >> 5, c4 = i & 31;
        int r = r0 + row;
        float4 v = make_float4(0.f, 0.f, 0.f, 0.f);
        if (r < n) {
            if (BN) {
                float4 a = unpack_h4(__ldg(&((const uint2*)(Xh + (size_t)r * 128))[c4]));
                float4 rr = __ldg(&((const float4*)(XRES + (size_t)r * 128))[c4]);
                int c = c4 * 4;
                v.x = fmaxf(fmaf(a.x, s_scale[c + 0], s_shift[c + 0]), 0.f) + rr.x;
                v.y = fmaxf(fmaf(a.y, s_scale[c + 1], s_shift[c + 1]), 0.f) + rr.y;
                v.z = fmaxf(fmaf(a.z, s_scale[c + 2], s_shift[c + 2]), 0.f) + rr.z;
                v.w = fmaxf(fmaf(a.w, s_scale[c + 3], s_shift[c + 3]), 0.f) + rr.w;
                ((uint2*)(XC + (size_t)r * 128))[c4] = pack_h4(v);
            } else {
                v = __ldg(&((const float4*)(Xf + (size_t)r * 128))[c4]);
            }
        }
        *(uint2*)(smem + A_OFF + (row * PAD + c4 * 4) * 2) = pack_h4(v);
    }
    __syncthreads();

    const int lane = tid & 31, wid = tid >> 5;
    const int m0 = (wid & 1) * 32;
    const int n0 = (wid >> 1) * 64;
    const uint32_t sb = smem_u32(smem);

    const uint32_t a_lane = (uint32_t)(lane & 15) * (PAD * 2) + ((lane & 16) ? 16u : 0u);
    const uint32_t b_lane = (uint32_t)(lane & 15) * (PAD * 2);

    float acc[2][8][4] = {};

    const uint32_t abase = sb + A_OFF + (uint32_t)m0 * (PAD * 2) + a_lane;
    const uint32_t bbase = sb + B_OFF + b_lane + (uint32_t)n0 * 2;
#pragma unroll
    for (int ks = 0; ks < 8; ks++) {
        uint32_t ar[2][4];
        ldsm_x4(ar[0], abase + ks * 32);
        ldsm_x4(ar[1], abase + 16 * PAD * 2 + ks * 32);
        const uint32_t bk = bbase + (uint32_t)ks * 16 * PAD * 2;
#pragma unroll
        for (int nt = 0; nt < 8; nt++) {
            uint32_t br[2];
            ldsm_x2t(br, bk + nt * 16);
            mma_f16(acc[0][nt], ar[0], br);
            mma_f16(acc[1][nt], ar[1], br);
        }
    }

    const int g = lane >> 2, tig = lane & 3;
#pragma unroll
    for (int mt = 0; mt < 2; mt++) {
#pragma unroll
        for (int half = 0; half < 2; half++) {
            int r = r0 + m0 + mt * 16 + g + half * 8;
            if (r < n) {
#pragma unroll
                for (int nt = 0; nt < 8; nt++) {
                    int c = n0 + nt * 8 + tig * 2;
                    *(__half2*)&H[(size_t)r * 128 + c] =
                        __floats2half2_rn(acc[mt][nt][half * 2], acc[mt][nt][half * 2 + 1]);
                }
            }
        }
    }
}

// ---------------- tensor-core GEMM 64x32x128 (final layer, fused BN input) ----------------
#define A32_OFF  0
#define B32_OFF  (64 * PAD * 2)                 // 17408
#define SC32_OFF (B32_OFF + 128 * BPAD32 * 2)   // 27648
#define MMA32_SMEM (SC32_OFF + 2 * FDIM * 4)    // 28672

__global__ void __launch_bounds__(128)
k_mma32(const __half* __restrict__ AGGH, const __half* __restrict__ W,
        __half* __restrict__ H2,
        const float* __restrict__ stats_sum, const float* __restrict__ stats_sumsq,
        const float* __restrict__ gam, const float* __restrict__ bet,
        const __half* __restrict__ XRES, int n) {
    extern __shared__ char smem[];
    float* s_scale = (float*)(smem + SC32_OFF);
    float* s_shift = s_scale + FDIM;
    const int tid = threadIdx.x;

    {
        float inv = 1.0f / (float)n;
        float mu = stats_sum[tid] * inv;
        float var = stats_sumsq[tid] * inv - mu * mu;
        float sc = rsqrtf(var + 1e-5f) * gam[tid];
        s_scale[tid] = sc;
        s_shift[tid] = bet[tid] - mu * sc;
    }
    for (int i = tid; i < 512; i += 128) {
        int row = i >> 2, c8 = i & 3;
        *(uint4*)(smem + B32_OFF + (row * BPAD32 + c8 * 8) * 2) = ((const uint4*)W)[i];
    }
    __syncthreads();

    const int r0 = (int)blockIdx.x * 64;
    for (int i = tid; i < 2048; i += 128) {
        int row = i >> 5, c4 = i & 31;
        int r = r0 + row;
        float4 v = make_float4(0.f, 0.f, 0.f, 0.f);
        if (r < n) {
            float4 a = unpack_h4(__ldg(&((const uint2*)(AGGH + (size_t)r * 128))[c4]));
            float4 rr = unpack_h4(__ldg(&((const uint2*)(XRES + (size_t)r * 128))[c4]));
            int c = c4 * 4;
            v.x = fmaxf(fmaf(a.x, s_scale[c + 0], s_shift[c + 0]), 0.f) + rr.x;
            v.y = fmaxf(fmaf(a.y, s_scale[c + 1], s_shift[c + 1]), 0.f) + rr.y;
            v.z = fmaxf(fmaf(a.z, s_scale[c + 2], s_shift[c + 2]), 0.f) + rr.z;
            v.w = fmaxf(fmaf(a.w, s_scale[c + 3], s_shift[c + 3]), 0.f) + rr.w;
        }
        *(uint2*)(smem + A32_OFF + (row * PAD + c4 * 4) * 2) = pack_h4(v);
    }
    __syncthreads();

    const int lane = tid & 31, wid = tid >> 5;
    const int m0 = (wid & 1) * 32;
    const int n0 = (wid >> 1) * 16;
    const uint32_t sb = smem_u32(smem);

    const uint32_t a_lane = (uint32_t)(lane & 15) * (PAD * 2) + ((lane & 16) ? 16u : 0u);
    const uint32_t b_lane = (uint32_t)(lane & 15) * (BPAD32 * 2);

    float acc[2][2][4] = {};

    const uint32_t abase = sb + A32_OFF + (uint32_t)m0 * (PAD * 2) + a_lane;
    const uint32_t bbase = sb + B32_OFF + b_lane + (uint32_t)n0 * 2;
#pragma unroll
    for (int ks = 0; ks < 8; ks++) {
        uint32_t ar[2][4];
        ldsm_x4(ar[0], abase + ks * 32);
        ldsm_x4(ar[1], abase + 16 * PAD * 2 + ks * 32);
        const uint32_t bk = bbase + (uint32_t)ks * 16 * BPAD32 * 2;
#pragma unroll
        for (int nt = 0; nt < 2; nt++) {
            uint32_t br[2];
            ldsm_x2t(br, bk + nt * 16);
            mma_f16(acc[0][nt], ar[0], br);
            mma_f16(acc[1][nt], ar[1], br);
        }
    }

    const int g = lane >> 2, tig = lane & 3;
#pragma unroll
    for (int mt = 0; mt < 2; mt++) {
#pragma unroll
        for (int half = 0; half < 2; half++) {
            int r = r0 + m0 + mt * 16 + g + half * 8;
            if (r < n) {
#pragma unroll
                for (int nt = 0; nt < 2; nt++) {
                    int c = n0 + nt * 8 + tig * 2;
                    *(__half2*)&H2[(size_t)r * 32 + c] =
                        __floats2half2_rn(acc[mt][nt][half * 2], acc[mt][nt][half * 2 + 1]);
                }
            }
        }
    }
}

// ---------------- CSR aggregation (128-wide, fp16 gather) + fused BN stats ----------------
__device__ __forceinline__ void acc_half8(float4& acc, const __half* __restrict__ row,
                                          int lane, float nrm) {
    uint2 u = ((const uint2*)row)[lane];
    float2 f0 = __half22float2(*(__half2*)&u.x);
    float2 f1 = __half22float2(*(__half2*)&u.y);
    acc.x = fmaf(f0.x, nrm, acc.x);
    acc.y = fmaf(f0.y, nrm, acc.y);
    acc.z = fmaf(f1.x, nrm, acc.z);
    acc.w = fmaf(f1.y, nrm, acc.w);
}

__global__ void k_agg128(const __half* __restrict__ H, const float* __restrict__ bias,
                         __half* __restrict__ AGGH, float* __restrict__ st_sum,
                         float* __restrict__ st_sumsq, int n) {
    __shared__ float s_rows[8][FDIM];
    __shared__ int s_valid[8];
    const int tid = threadIdx.x;
    const int lane = tid & 31, wid = tid >> 5;
    int v = (blockIdx.x * blockDim.x + tid) >> 5;
    const bool valid = (v < n);
    if (lane == 0) s_valid[wid] = valid ? 1 : 0;

    float4 acc = make_float4(0.f, 0.f, 0.f, 0.f);
    if (valid) {
        const float dv = g_dis[v];
        const int e0 = g_off[v], e1 = g_off[v + 1];
        acc = ((const float4*)bias)[lane];
        acc_half8(acc, H + (size_t)v * FDIM, lane, dv * dv);
        int e = e0;
        for (; e + 1 < e1; e += 2) {
            int s0 = __ldg(&g_esrc[e]);
            int s1 = __ldg(&g_esrc[e + 1]);
            float n0 = g_dis[s0] * dv;
            float n1 = g_dis[s1] * dv;
            acc_half8(acc, H + (size_t)s0 * FDIM, lane, n0);
            acc_half8(acc, H + (size_t)s1 * FDIM, lane, n1);
        }
        if (e < e1) {
            int s0 = __ldg(&g_esrc[e]);
            acc_half8(acc, H + (size_t)s0 * FDIM, lane, g_dis[s0] * dv);
        }
        ((uint2*)(AGGH + (size_t)v * FDIM))[lane] = pack_h4(acc);
    }
    *(float4*)&s_rows[wid][lane * 4] = acc;
    __syncthreads();

    int c = tid & 127;
    int part = tid >> 7;
    float s = 0.0f;
#pragma unroll
    for (int w = 0; w < 8; w++) {
        if (s_valid[w]) {
            float val = s_rows[w][c];
            s += part ? val * val : val;
        }
    }
    atomicAdd(part ? &st_sumsq[c] : &st_sum[c], s);
}

// ---------------- CSR aggregation (32-wide fp16) fused with log_softmax ----------------
__global__ void k_agg32_lsm(const __half* __restrict__ H2, const float* __restrict__ bias,
                            float* __restrict__ out, int n) {
    int v = (blockIdx.x * blockDim.x + threadIdx.x) >> 5;
    if (v >= n) return;
    const int lane = threadIdx.x & 31;
    const float dv = g_dis[v];
    const int e0 = g_off[v], e1 = g_off[v + 1];

    float acc = bias[lane] + __half2float(H2[(size_t)v * ODIM + lane]) * dv * dv;
    int e = e0;
    for (; e + 1 < e1; e += 2) {
        int s0 = __ldg(&g_esrc[e]);
        int s1 = __ldg(&g_esrc[e + 1]);
        float n0 = g_dis[s0] * dv;
        float n1 = g_dis[s1] * dv;
        float a = __half2float(H2[(size_t)s0 * ODIM + lane]);
        float b = __half2float(H2[(size_t)s1 * ODIM + lane]);
        acc = fmaf(a, n0, acc);
        acc = fmaf(b, n1, acc);
    }
    if (e < e1) {
        int s0 = __ldg(&g_esrc[e]);
        acc = fmaf(__half2float(H2[(size_t)s0 * ODIM + lane]), g_dis[s0] * dv, acc);
    }
    float m = acc;
#pragma unroll
    for (int o = 16; o; o >>= 1) m = fmaxf(m, __shfl_xor_sync(0xffffffffu, m, o));
    float ex = expf(acc - m);
    float s = ex;
#pragma unroll
    for (int o = 16; o; o >>= 1) s += __shfl_xor_sync(0xffffffffu, s, o);
    out[(size_t)v * ODIM + lane] = acc - m - logf(s);
}

// ---------------- launch ----------------
extern "C" void kernel_launch(void* const* d_in, const int* in_sizes, int n_in,
                              void* d_out, int out_size) {
    const float* x   = (const float*)d_in[0];
    const void*  ei  = d_in[1];
    const float* W0  = (const float*)d_in[2];
    const float* b0  = (const float*)d_in[3];
    const float* gm0 = (const float*)d_in[4];
    const float* be0 = (const float*)d_in[5];
    const float* W1  = (const float*)d_in[6];
    const float* b1  = (const float*)d_in[7];
    const float* gm1 = (const float*)d_in[8];
    const float* be1 = (const float*)d_in[9];
    const float* W2  = (const float*)d_in[10];
    const float* b2  = (const float*)d_in[11];
    float* out = (float*)d_out;

    const int n = in_sizes[0] / FDIM;   // 50000
    const int E = in_sizes[1] / 2;      // 800000

    __half *p_h, *p_aggh, *p_xc, *p_h2, *p_wh;
    float *p_sum, *p_sumsq;
    cudaGetSymbolAddress((void**)&p_h, g_h);
    cudaGetSymbolAddress((void**)&p_aggh, g_aggh);
    cudaGetSymbolAddress((void**)&p_xc, g_xc);
    cudaGetSymbolAddress((void**)&p_h2, g_h2);
    cudaGetSymbolAddress((void**)&p_sum, g_sum);
    cudaGetSymbolAddress((void**)&p_sumsq, g_sumsq);
    cudaGetSymbolAddress((void**)&p_wh, g_wh);

    cudaFuncSetAttribute(k_mma128<0>, cudaFuncAttributeMaxDynamicSharedMemorySize, MMA_SMEM);
    cudaFuncSetAttribute(k_mma128<1>, cudaFuncAttributeMaxDynamicSharedMemorySize, MMA_SMEM);
    cudaFuncSetAttribute(k_mma32,     cudaFuncAttributeMaxDynamicSharedMemorySize, MMA32_SMEM);

    const int node_warp_blocks = (n + 7) / 8;
    const int mma_blocks = (n + 63) / 64;

    const bool fork = (g_s1 != 0) && (g_evF != 0) && (g_evJ != 0);
    cudaStream_t sB = fork ? g_s1 : 0;

    // ---- fork: branch B = W convert + layer-0 GEMM (independent of CSR build) ----
    if (fork) {
        cudaEventRecord(g_evF, 0);
        cudaStreamWaitEvent(sB, g_evF, 0);
    }
    k_wconv<<<144, 256, 0, sB>>>(W0, W1, W2);
    k_mma128<0><<<mma_blocks, 128, MMA_SMEM, sB>>>(x, nullptr, p_wh, p_h,
                                                   nullptr, nullptr, nullptr, nullptr,
                                                   nullptr, nullptr, n);
    if (fork) cudaEventRecord(g_evJ, sB);

    // ---- branch A (main stream): CSR build ----
    k_pre0<<<(NNODES + 255) / 256, 256>>>((const unsigned*)ei);
    k_hist<<<(E + 255) / 256, 256>>>(ei, E);
    k_bsum<<<NSCANB, 256>>>();
    k_offs<<<NSCANB, 256>>>();
    k_fill<<<(E + 255) / 256, 256>>>(ei, E);

    // ---- join ----
    if (fork) cudaStreamWaitEvent(0, g_evJ, 0);

    // ---- layer 0 aggregate ----
    k_agg128<<<node_warp_blocks, 256>>>(p_h, b0, p_aggh, p_sum, p_sumsq, n);

    // ---- layer 1 ----
    k_mma128<1><<<mma_blocks, 128, MMA_SMEM>>>(nullptr, p_aggh, p_wh + 16384, p_h,
                                               p_sum, p_sumsq, gm0, be0, x, p_xc, n);
    k_agg128<<<node_warp_blocks, 256>>>(p_h, b1, p_aggh, p_sum + FDIM, p_sumsq + FDIM, n);

    // ---- final ----
    k_mma32<<<mma_blocks, 128, MMA32_SMEM>>>(p_aggh, p_wh + 32768, p_h2,
                                             p_sum + FDIM, p_sumsq + FDIM, gm1, be1, p_xc, n);
    k_agg32_lsm<<<node_warp_blocks, 256>>>(p_h2, b2, out, n);
}